// round 4
// baseline (speedup 1.0000x reference)
#include <cuda_runtime.h>

// ---------------- problem constants ----------------
#define N_NODES 10000
#define N_RELS  50
#define R_AUG   101                    // 2*N_RELS + 1
#define D       128
#define N_EDGES 320000
#define E_AUG   (2*N_EDGES + N_NODES)  // 650000
#define N_SEG   (R_AUG * N_NODES)      // 1010000
#define N_BATCH 65536

// scan config
#define SCAN_B  1024
#define NB_SCAN ((N_SEG + SCAN_B - 1) / SCAN_B)   // 987

// layer-gemm config
#define NS   8            // relation splits
#define RPS  13           // rels per split (ceil(101/8))
#define TM   128
#define NTILES ((N_NODES + TM - 1) / TM)          // 79
#define SAS  129          // sA row stride (pad 1 to dodge bank conflicts)
#define LAYER_SMEM ((TM*SAS + D*D) * 4)           // 131584 bytes

typedef unsigned long long u64;

// ---------------- static device scratch (no allocation allowed) ----------------
__device__ int   g_deg[N_SEG];
__device__ int   g_rowptr[N_SEG + 1];
__device__ int   g_cursor[N_SEG];
__device__ int   g_bsums[NB_SCAN];
__device__ int   g_csr[E_AUG];
__device__ float g_h1[N_NODES * D];
__device__ float g_h2[N_NODES * D];
__device__ float g_partial[(size_t)NS * N_NODES * D];   // 41 MB

// ---------------- packed fp32x2 helpers (Blackwell) ----------------
__device__ __forceinline__ u64 splat2(float a) {
    u64 r;
    asm("mov.b64 %0, {%1, %1};" : "=l"(r) : "f"(a));
    return r;
}
__device__ __forceinline__ void fma2(u64& c, u64 a, u64 b) {
    asm("fma.rn.f32x2 %0, %1, %2, %0;" : "+l"(c) : "l"(a), "l"(b));
}

// ---------------- CSR build ----------------
__global__ void zero_deg_kernel() {
    int i = blockIdx.x * blockDim.x + threadIdx.x;
    if (i < N_SEG) g_deg[i] = 0;
}

__device__ __forceinline__ void aug_edge(const int* __restrict__ g, int e,
                                         int& seg, int& src) {
    if (e < N_EDGES) {
        int s = g[e * 3 + 0], p = g[e * 3 + 1], o = g[e * 3 + 2];
        seg = p * N_NODES + o;  src = s;
    } else if (e < 2 * N_EDGES) {
        int e2 = e - N_EDGES;
        int s = g[e2 * 3 + 0], p = g[e2 * 3 + 1], o = g[e2 * 3 + 2];
        seg = (p + N_RELS) * N_NODES + s;  src = o;
    } else {
        int i = e - 2 * N_EDGES;
        seg = 2 * N_RELS * N_NODES + i;    src = i;
    }
}

__global__ void hist_kernel(const int* __restrict__ g) {
    int e = blockIdx.x * blockDim.x + threadIdx.x;
    if (e >= E_AUG) return;
    int seg, src;
    aug_edge(g, e, seg, src);
    atomicAdd(&g_deg[seg], 1);
}

__global__ __launch_bounds__(SCAN_B) void scan_local_kernel() {
    __shared__ int sm[SCAN_B];
    int tid = threadIdx.x;
    int gidx = blockIdx.x * SCAN_B + tid;
    int v = (gidx < N_SEG) ? g_deg[gidx] : 0;
    sm[tid] = v;
    __syncthreads();
    #pragma unroll
    for (int off = 1; off < SCAN_B; off <<= 1) {
        int t = (tid >= off) ? sm[tid - off] : 0;
        __syncthreads();
        sm[tid] += t;
        __syncthreads();
    }
    int incl = sm[tid];
    if (gidx < N_SEG) g_rowptr[gidx] = incl - v;   // local exclusive
    if (tid == SCAN_B - 1) g_bsums[blockIdx.x] = incl;
}

__global__ __launch_bounds__(SCAN_B) void scan_sums_kernel() {
    __shared__ int sm[SCAN_B];
    int tid = threadIdx.x;
    int v = (tid < NB_SCAN) ? g_bsums[tid] : 0;
    sm[tid] = v;
    __syncthreads();
    #pragma unroll
    for (int off = 1; off < SCAN_B; off <<= 1) {
        int t = (tid >= off) ? sm[tid - off] : 0;
        __syncthreads();
        sm[tid] += t;
        __syncthreads();
    }
    if (tid < NB_SCAN) g_bsums[tid] = sm[tid] - v;  // exclusive
}

__global__ __launch_bounds__(SCAN_B) void scan_add_kernel() {
    int tid = threadIdx.x;
    int gidx = blockIdx.x * SCAN_B + tid;
    if (gidx < N_SEG) {
        int v = g_rowptr[gidx] + g_bsums[blockIdx.x];
        g_rowptr[gidx] = v;
        g_cursor[gidx] = v;       // scatter cursors start at row offsets
    }
    if (blockIdx.x == 0 && tid == 0) g_rowptr[N_SEG] = E_AUG;
}

__global__ void scatter_kernel(const int* __restrict__ g) {
    int e = blockIdx.x * blockDim.x + threadIdx.x;
    if (e >= E_AUG) return;
    int seg, src;
    aug_edge(g, e, seg, src);
    int pos = atomicAdd(&g_cursor[seg], 1);
    g_csr[pos] = src;
}

// ---------------- fused aggregate + per-relation GEMM ----------------
// grid: (NTILES, NS).  Each CTA: 128-node tile x full 128 output dims,
// looping its relation slice; agg tile built in SMEM from CSR; acc in regs.
extern "C" __global__ void __launch_bounds__(256, 1)
layer_kernel(const float* __restrict__ x, const float* __restrict__ W) {
    extern __shared__ float smem[];
    float* sA = smem;            // [TM][SAS] agg tile (node-major)
    float* sB = smem + TM * SAS; // [D][D]  W_r (k-major rows)

    int tid  = threadIdx.x;
    int lane = tid & 31, warp = tid >> 5;
    int tx = tid & 15, ty = tid >> 4;
    int tileBase = blockIdx.x * TM;
    int relStart = blockIdx.y * RPS;
    int relEnd   = min(relStart + RPS, R_AUG);

    u64 acc[8][4];
    #pragma unroll
    for (int i = 0; i < 8; i++)
        #pragma unroll
        for (int j = 0; j < 4; j++) acc[i][j] = 0ull;

    for (int r = relStart; r < relEnd; ++r) {
        __syncthreads();   // prior GEMM done reading smem

        // ---- build agg tile: warp per row, lane owns 4 dims (float4) ----
        #pragma unroll 1
        for (int t = 0; t < 16; t++) {
            int m = warp + (t << 3);
            int node = tileBase + m;
            float4 a4 = make_float4(0.f, 0.f, 0.f, 0.f);
            if (node < N_NODES) {
                int seg = r * N_NODES + node;
                int s = g_rowptr[seg], e = g_rowptr[seg + 1];
                for (int j = s; j < e; ++j) {
                    int src = g_csr[j];
                    float4 v = ((const float4*)(x + (size_t)src * D))[lane];
                    a4.x += v.x; a4.y += v.y; a4.z += v.z; a4.w += v.w;
                }
                float nrm = 1.0f / fmaxf((float)(e - s), 1.0f);
                a4.x *= nrm; a4.y *= nrm; a4.z *= nrm; a4.w *= nrm;
            }
            float* row = sA + m * SAS + (lane << 2);
            row[0] = a4.x; row[1] = a4.y; row[2] = a4.z; row[3] = a4.w;
        }

        // ---- stage W_r ----
        {
            const float4* Wr = (const float4*)(W + (size_t)r * (D * D));
            float4* sB4 = (float4*)sB;
            #pragma unroll
            for (int i = 0; i < 16; i++) sB4[tid + i * 256] = Wr[tid + i * 256];
        }
        __syncthreads();

        // ---- 128x128x128 GEMM, fp32x2 packed FMA ----
        const float* sBtx = sB + tx * 8;
        #pragma unroll 4
        for (int k = 0; k < D; ++k) {
            float a[8];
            #pragma unroll
            for (int i = 0; i < 8; i++) a[i] = sA[(ty * 8 + i) * SAS + k];
            u64 b[4];
            const u64* brow = (const u64*)(sBtx + k * D);
            #pragma unroll
            for (int j = 0; j < 4; j++) b[j] = brow[j];
            #pragma unroll
            for (int i = 0; i < 8; i++) {
                u64 a2 = splat2(a[i]);
                #pragma unroll
                for (int j = 0; j < 4; j++) fma2(acc[i][j], a2, b[j]);
            }
        }
    }

    // ---- write partial slab for this split ----
    float* base = g_partial + (size_t)blockIdx.y * (N_NODES * D);
    #pragma unroll
    for (int i = 0; i < 8; i++) {
        int node = tileBase + ty * 8 + i;
        if (node < N_NODES) {
            float* p = base + (size_t)node * D + tx * 8;
            const float* af = (const float*)acc[i];
            float4 v0 = make_float4(af[0], af[1], af[2], af[3]);
            float4 v1 = make_float4(af[4], af[5], af[6], af[7]);
            ((float4*)p)[0] = v0;
            ((float4*)p)[1] = v1;
        }
    }
}

// ---------------- reduce splits + bias (+relu) ----------------
__global__ void reduce_kernel(const float* __restrict__ bias,
                              float* __restrict__ out, int do_relu) {
    int i = blockIdx.x * blockDim.x + threadIdx.x;   // float4 index
    const int n4 = N_NODES * D / 4;                   // 320000
    if (i >= n4) return;
    const float4* p4 = (const float4*)g_partial;
    float4 s = p4[i];
    #pragma unroll
    for (int k = 1; k < NS; k++) {
        float4 t = p4[i + (size_t)k * n4];
        s.x += t.x; s.y += t.y; s.z += t.z; s.w += t.w;
    }
    float4 b = ((const float4*)bias)[i & 31];
    s.x += b.x; s.y += b.y; s.z += b.z; s.w += b.w;
    if (do_relu) {
        s.x = fmaxf(s.x, 0.f); s.y = fmaxf(s.y, 0.f);
        s.z = fmaxf(s.z, 0.f); s.w = fmaxf(s.w, 0.f);
    }
    ((float4*)out)[i] = s;
}

// ---------------- scoring: warp per batch item ----------------
__global__ void score_kernel(const int* __restrict__ batch,
                             const float* __restrict__ xn,
                             const float* __restrict__ rels,
                             float* __restrict__ out) {
    int w = (blockIdx.x * blockDim.x + threadIdx.x) >> 5;
    int lane = threadIdx.x & 31;
    if (w >= N_BATCH) return;
    int bs = batch[w * 3 + 0], bp = batch[w * 3 + 1], bo = batch[w * 3 + 2];
    float4 a = ((const float4*)(xn + (size_t)bs * D))[lane];
    float4 r = ((const float4*)(rels + (size_t)bp * D))[lane];
    float4 c = ((const float4*)(xn + (size_t)bo * D))[lane];
    float s = a.x * r.x * c.x + a.y * r.y * c.y + a.z * r.z * c.z + a.w * r.w * c.w;
    #pragma unroll
    for (int o = 16; o; o >>= 1) s += __shfl_xor_sync(0xffffffffu, s, o);
    if (lane == 0) out[w] = s;
}

// ---------------- launch ----------------
extern "C" void kernel_launch(void* const* d_in, const int* in_sizes, int n_in,
                              void* d_out, int out_size) {
    const int*   graph = (const int*)d_in[0];
    const int*   batch = (const int*)d_in[1];
    const float* x0    = (const float*)d_in[2];
    const float* W1    = (const float*)d_in[3];
    const float* b1    = (const float*)d_in[4];
    const float* W2    = (const float*)d_in[5];
    const float* b2    = (const float*)d_in[6];
    const float* rels  = (const float*)d_in[7];
    float* out = (float*)d_out;

    void *p_h1 = nullptr, *p_h2 = nullptr;
    cudaGetSymbolAddress(&p_h1, g_h1);
    cudaGetSymbolAddress(&p_h2, g_h2);
    float* h1 = (float*)p_h1;
    float* h2 = (float*)p_h2;

    cudaFuncSetAttribute(layer_kernel,
                         cudaFuncAttributeMaxDynamicSharedMemorySize, LAYER_SMEM);

    // CSR build (shared by both layers)
    zero_deg_kernel<<<(N_SEG + 255) / 256, 256>>>();
    hist_kernel<<<(E_AUG + 255) / 256, 256>>>(graph);
    scan_local_kernel<<<NB_SCAN, SCAN_B>>>();
    scan_sums_kernel<<<1, SCAN_B>>>();
    scan_add_kernel<<<NB_SCAN, SCAN_B>>>();
    scatter_kernel<<<(E_AUG + 255) / 256, 256>>>(graph);

    dim3 lgrid(NTILES, NS);

    // layer 1
    layer_kernel<<<lgrid, 256, LAYER_SMEM>>>(x0, W1);
    reduce_kernel<<<(N_NODES * D / 4 + 255) / 256, 256>>>(b1, h1, 1);

    // layer 2
    layer_kernel<<<lgrid, 256, LAYER_SMEM>>>(h1, W2);
    reduce_kernel<<<(N_NODES * D / 4 + 255) / 256, 256>>>(b2, h2, 0);

    // scoring
    score_kernel<<<(N_BATCH * 32) / 256, 256>>>(batch, h2, rels, out);
}

// round 6
// speedup vs baseline: 1.5242x; 1.5242x over previous
#include <cuda_runtime.h>
#include <cuda_bf16.h>

// ---------------- problem constants ----------------
#define N_NODES 10000
#define N_RELS  50
#define R_AUG   101                    // 2*N_RELS + 1
#define D       128
#define N_EDGES 320000
#define E_AUG   (2*N_EDGES + N_NODES)  // 650000
#define N_SEG   (R_AUG * N_NODES)      // 1010000
#define N_BATCH 65536

// scan config
#define SCAN_B  1024
#define NB_SCAN ((N_SEG + SCAN_B - 1) / SCAN_B)   // 987

// persistent layer config
#define TM      128
#define NTILES  ((N_NODES + TM - 1) / TM)          // 79
#define NITEMS  (NTILES * R_AUG)                   // 7979
#define NCTA    148
#define WPC     ((NITEMS + NCTA - 1) / NCTA)       // 54
#define NSLAB   3
#define ECHUNK  1024

// bf16 tile row stride: 128 + 8 pad = 136 elements = 272 bytes (17 * 16B)
#define TS      272

// smem layout (bytes)
#define OFF_AF   0                          // fp32 staging [128][128]   65536
#define OFF_AH   65536                      // bf16 A hi [128][136]      34816
#define OFF_AL   (OFF_AH + 34816)           // bf16 A lo                 34816
#define OFF_BH   (OFF_AL + 34816)           // bf16 B hi (Wr^T)          34816
#define OFF_BL   (OFF_BH + 34816)           // bf16 B lo                 34816
#define OFF_ED   (OFF_BL + 34816)           // edge buffer int2          8192
#define OFF_NRM  (OFF_ED + ECHUNK*8)        // 128 floats                512
#define OFF_SPAN (OFF_NRM + 512)
#define SMEM_TOT (OFF_SPAN + 64)            // ~213.6 KB

typedef unsigned long long u64;
typedef unsigned int u32;

// ---------------- static device scratch ----------------
__device__ int   g_deg[N_SEG];
__device__ int   g_rowptr[N_SEG + 1];
__device__ int   g_cursor[N_SEG];
__device__ int   g_bsums[NB_SCAN];
__device__ int2  g_csr2[E_AUG];                        // (src, dst)
__device__ unsigned short g_Bt[(size_t)R_AUG * 32768]; // per rel: hi[128][128] | lo[128][128], row=n, col=k
__device__ float g_h1[N_NODES * D];
__device__ float g_h2[N_NODES * D];
__device__ float g_partial[(size_t)NSLAB * N_NODES * D];

// ---------------- small helpers ----------------
__device__ __forceinline__ u32 smem_u32(const void* p) {
    u32 a;
    asm("{ .reg .u64 t; cvta.to.shared.u64 t, %1; cvt.u32.u64 %0, t; }" : "=r"(a) : "l"(p));
    return a;
}
__device__ __forceinline__ unsigned short f2bf(float v) {
    return __bfloat16_as_ushort(__float2bfloat16_rn(v));
}
__device__ __forceinline__ float bf2f(unsigned short u) {
    return __bfloat162float(__ushort_as_bfloat16(u));
}

#define LDSM4(r, addr)                                                          \
    asm volatile("ldmatrix.sync.aligned.m8n8.x4.shared.b16 {%0,%1,%2,%3}, [%4];"\
        : "=r"((r)[0]), "=r"((r)[1]), "=r"((r)[2]), "=r"((r)[3]) : "r"(addr))

#define MMA16816(c, a, b0_, b1_)                                                \
    asm volatile("mma.sync.aligned.m16n8k16.row.col.f32.bf16.bf16.f32 "         \
        "{%0,%1,%2,%3}, {%4,%5,%6,%7}, {%8,%9}, {%0,%1,%2,%3};"                 \
        : "+f"((c)[0]), "+f"((c)[1]), "+f"((c)[2]), "+f"((c)[3])                \
        : "r"((a)[0]), "r"((a)[1]), "r"((a)[2]), "r"((a)[3]), "r"(b0_), "r"(b1_))

// ---------------- CSR build ----------------
__global__ void zero_deg_kernel() {
    int i = blockIdx.x * blockDim.x + threadIdx.x;
    if (i < N_SEG) g_deg[i] = 0;
}

__device__ __forceinline__ void aug_edge(const int* __restrict__ g, int e,
                                         int& seg, int& src, int& dst) {
    if (e < N_EDGES) {
        int s = g[e*3+0], p = g[e*3+1], o = g[e*3+2];
        seg = p * N_NODES + o;  src = s;  dst = o;
    } else if (e < 2*N_EDGES) {
        int e2 = e - N_EDGES;
        int s = g[e2*3+0], p = g[e2*3+1], o = g[e2*3+2];
        seg = (p + N_RELS) * N_NODES + s;  src = o;  dst = s;
    } else {
        int i = e - 2*N_EDGES;
        seg = 2*N_RELS*N_NODES + i;  src = i;  dst = i;
    }
}

__global__ void hist_kernel(const int* __restrict__ g) {
    int e = blockIdx.x * blockDim.x + threadIdx.x;
    if (e >= E_AUG) return;
    int seg, src, dst;
    aug_edge(g, e, seg, src, dst);
    atomicAdd(&g_deg[seg], 1);
}

__global__ __launch_bounds__(SCAN_B) void scan_local_kernel() {
    __shared__ int sm[SCAN_B];
    int tid = threadIdx.x;
    int gidx = blockIdx.x * SCAN_B + tid;
    int v = (gidx < N_SEG) ? g_deg[gidx] : 0;
    sm[tid] = v;
    __syncthreads();
    #pragma unroll
    for (int off = 1; off < SCAN_B; off <<= 1) {
        int t = (tid >= off) ? sm[tid - off] : 0;
        __syncthreads();
        sm[tid] += t;
        __syncthreads();
    }
    int incl = sm[tid];
    if (gidx < N_SEG) g_rowptr[gidx] = incl - v;
    if (tid == SCAN_B - 1) g_bsums[blockIdx.x] = incl;
}

__global__ __launch_bounds__(SCAN_B) void scan_sums_kernel() {
    __shared__ int sm[SCAN_B];
    int tid = threadIdx.x;
    int v = (tid < NB_SCAN) ? g_bsums[tid] : 0;
    sm[tid] = v;
    __syncthreads();
    #pragma unroll
    for (int off = 1; off < SCAN_B; off <<= 1) {
        int t = (tid >= off) ? sm[tid - off] : 0;
        __syncthreads();
        sm[tid] += t;
        __syncthreads();
    }
    if (tid < NB_SCAN) g_bsums[tid] = sm[tid] - v;
}

__global__ __launch_bounds__(SCAN_B) void scan_add_kernel() {
    int tid = threadIdx.x;
    int gidx = blockIdx.x * SCAN_B + tid;
    if (gidx < N_SEG) {
        int v = g_rowptr[gidx] + g_bsums[blockIdx.x];
        g_rowptr[gidx] = v;
        g_cursor[gidx] = v;
    }
    if (blockIdx.x == 0 && tid == 0) g_rowptr[N_SEG] = E_AUG;
}

__global__ void scatter_kernel(const int* __restrict__ g) {
    int e = blockIdx.x * blockDim.x + threadIdx.x;
    if (e >= E_AUG) return;
    int seg, src, dst;
    aug_edge(g, e, seg, src, dst);
    int pos = atomicAdd(&g_cursor[seg], 1);
    g_csr2[pos] = make_int2(src, dst);
}

// ---------------- W -> bf16 hi/lo B^T planes (row=n, col=k) ----------------
__global__ void convert_w_kernel(const float* __restrict__ W) {
    int r = blockIdx.x;
    const float* Wr = W + (size_t)r * (D * D);
    unsigned short* Bt = g_Bt + (size_t)r * 32768;
    for (int idx = threadIdx.x; idx < D * D; idx += blockDim.x) {
        int k = idx >> 7, n = idx & 127;
        float v = Wr[k * D + n];
        unsigned short h = f2bf(v);
        unsigned short l = f2bf(v - bf2f(h));
        Bt[n * D + k]         = h;
        Bt[16384 + n * D + k] = l;
    }
}

__global__ void zero_partial_kernel() {
    int i = blockIdx.x * blockDim.x + threadIdx.x;
    const int n4 = NSLAB * N_NODES * D / 4;
    if (i < n4) ((float4*)g_partial)[i] = make_float4(0.f, 0.f, 0.f, 0.f);
}

// ---------------- flush register accumulators to a partial slab ----------------
__device__ __forceinline__ void flush_acc(float acc[2][8][4], int cur_t,
                                          int warp, int lane) {
    int slab_i = blockIdx.x - (cur_t * R_AUG) / WPC;
    float* slab = g_partial + (size_t)slab_i * (N_NODES * D);
    int wm = warp & 3, wn = warp >> 2;
    int r0 = cur_t * TM + wm * 32 + (lane >> 2);
    int cb = wn * 64 + (lane & 3) * 2;
    #pragma unroll
    for (int mf = 0; mf < 2; mf++) {
        int rowA = r0 + mf * 16;
        int rowB = rowA + 8;
        #pragma unroll
        for (int nf = 0; nf < 8; nf++) {
            int col = cb + nf * 8;
            if (rowA < N_NODES)
                *(float2*)(slab + (size_t)rowA * D + col) =
                    make_float2(acc[mf][nf][0], acc[mf][nf][1]);
            if (rowB < N_NODES)
                *(float2*)(slab + (size_t)rowB * D + col) =
                    make_float2(acc[mf][nf][2], acc[mf][nf][3]);
        }
    }
}

// ---------------- persistent fused aggregate + HMMA split-bf16 GEMM ----------------
extern "C" __global__ void __launch_bounds__(256, 1)
layer_tc_kernel(const float* __restrict__ x) {
    extern __shared__ char smem[];
    u32 smb = smem_u32(smem);
    float* sAf   = (float*)(smem + OFF_AF);
    int2*  sEd   = (int2*)(smem + OFF_ED);
    float* snrm  = (float*)(smem + OFF_NRM);
    int*   sSpan = (int*)(smem + OFF_SPAN);

    int tid  = threadIdx.x;
    int warp = tid >> 5, lane = tid & 31;
    int wm = warp & 3, wn = warp >> 2;

    // ldmatrix per-lane row offsets (bytes) within a tile
    u32 rowa = (u32)(wm * 32 + (lane & 15)) * TS + (u32)((lane >> 4) << 3) * 2;
    u32 rowb = (u32)(wn * 64 + ((lane >> 4) << 3) + (lane & 7)) * TS
             + (u32)(((lane >> 3) & 1) << 3) * 2;
    u32 aHb = smb + OFF_AH + rowa, aLb = smb + OFF_AL + rowa;
    u32 bHb = smb + OFF_BH + rowb, bLb = smb + OFF_BL + rowb;

    float acc[2][8][4];
    #pragma unroll
    for (int i = 0; i < 2; i++)
        #pragma unroll
        for (int j = 0; j < 8; j++)
            #pragma unroll
            for (int q = 0; q < 4; q++) acc[i][j][q] = 0.f;

    int i0 = blockIdx.x * WPC;
    int i1 = min(i0 + WPC, NITEMS);
    if (i0 >= i1) return;

    int cur_t = -1;

    for (int it = i0; it < i1; ++it) {
        int t = it / R_AUG, r = it - t * R_AUG;
        int tb = t * TM;
        int nrows = min(TM, N_NODES - tb);
        int segbase = r * N_NODES + tb;

        if (t != cur_t) {
            if (cur_t >= 0) {
                flush_acc(acc, cur_t, warp, lane);
                #pragma unroll
                for (int i = 0; i < 2; i++)
                    #pragma unroll
                    for (int j = 0; j < 8; j++)
                        #pragma unroll
                        for (int q = 0; q < 4; q++) acc[i][j][q] = 0.f;
            }
            cur_t = t;
        }

        // ---- (A) zero fp32 staging + norms + span ----
        {
            float4 z4 = make_float4(0.f, 0.f, 0.f, 0.f);
            float4* z = (float4*)sAf;
            #pragma unroll
            for (int q = 0; q < 16; q++) z[tid + q * 256] = z4;
        }
        if (tid < TM) {
            int dg = 0;
            if (tid < nrows) dg = g_rowptr[segbase + tid + 1] - g_rowptr[segbase + tid];
            snrm[tid] = 1.0f / fmaxf((float)dg, 1.0f);
        }
        if (tid == 0) { sSpan[0] = g_rowptr[segbase]; sSpan[1] = g_rowptr[segbase + nrows]; }
        __syncthreads();

        // ---- (B) edge-parallel build: warp per edge, lane per float4 chunk ----
        int eS = sSpan[0], eE = sSpan[1];
        for (int cb = eS; cb < eE; cb += ECHUNK) {
            int nC = min(ECHUNK, eE - cb);
            for (int j = tid; j < nC; j += 256) sEd[j] = g_csr2[cb + j];
            __syncthreads();
            int nT = nC * 32;
            #pragma unroll 2
            for (int tt = tid; tt < nT; tt += 256) {
                int e = tt >> 5, c = tt & 31;
                int2 ed = sEd[e];
                float4 v = ((const float4*)(x + (size_t)ed.x * D))[c];
                float* row = sAf + (ed.y - tb) * D + (c << 2);
                atomicAdd(row + 0, v.x); atomicAdd(row + 1, v.y);
                atomicAdd(row + 2, v.z); atomicAdd(row + 3, v.w);
            }
            __syncthreads();
        }
        __syncthreads();   // all warps done with previous GEMM reads + build writes

        // ---- (C) convert staging -> bf16 hi/lo A tiles (row-rotated, conflict-light) ----
        {
            int row = tid >> 1;
            int half = tid & 1;
            float nrm = snrm[row];
            const float* af = sAf + row * D + half * 64;
            char* AH = smem + OFF_AH + row * TS + half * 128;
            char* AL = smem + OFF_AL + row * TS + half * 128;
            #pragma unroll
            for (int ci = 0; ci < 32; ci++) {
                int c = (((ci + row) & 31) << 1);
                float v0 = af[c] * nrm, v1 = af[c + 1] * nrm;
                unsigned short h0 = f2bf(v0), h1 = f2bf(v1);
                unsigned short l0 = f2bf(v0 - bf2f(h0)), l1 = f2bf(v1 - bf2f(h1));
                *(u32*)(AH + c * 2) = (u32)h0 | ((u32)h1 << 16);
                *(u32*)(AL + c * 2) = (u32)l0 | ((u32)l1 << 16);
            }
        }
        // ---- stage B hi/lo tiles (re-pad 256B rows -> 272B rows) ----
        {
            const uint4* srcH = (const uint4*)(g_Bt + (size_t)r * 32768);
            const uint4* srcL = (const uint4*)(g_Bt + (size_t)r * 32768 + 16384);
            #pragma unroll
            for (int q = 0; q < 8; q++) {
                int idx = tid + q * 256;            // 0..2047 uint4
                int row = idx >> 4, c16 = idx & 15;
                *(uint4*)(smem + OFF_BH + row * TS + c16 * 16) = srcH[idx];
                *(uint4*)(smem + OFF_BL + row * TS + c16 * 16) = srcL[idx];
            }
        }
        __syncthreads();

        // ---- (D) 128x128x128 GEMM, 3-term bf16 split on HMMA ----
        #pragma unroll
        for (int ks = 0; ks < 8; ks++) {
            u32 k2 = (u32)ks * 32;                  // k0 * 2 bytes
            u32 aH0[4], aH1[4], aL0[4], aL1[4];
            LDSM4(aH0, aHb + k2);
            LDSM4(aH1, aHb + 16 * TS + k2);
            LDSM4(aL0, aLb + k2);
            LDSM4(aL1, aLb + 16 * TS + k2);
            #pragma unroll
            for (int nf2 = 0; nf2 < 4; nf2++) {
                u32 bH[4], bL[4];
                LDSM4(bH, bHb + (u32)nf2 * 16 * TS + k2);
                LDSM4(bL, bLb + (u32)nf2 * 16 * TS + k2);
                int n0 = nf2 * 2, n1 = nf2 * 2 + 1;
                MMA16816(acc[0][n0], aH0, bH[0], bH[1]);
                MMA16816(acc[0][n0], aL0, bH[0], bH[1]);
                MMA16816(acc[0][n0], aH0, bL[0], bL[1]);
                MMA16816(acc[1][n0], aH1, bH[0], bH[1]);
                MMA16816(acc[1][n0], aL1, bH[0], bH[1]);
                MMA16816(acc[1][n0], aH1, bL[0], bL[1]);
                MMA16816(acc[0][n1], aH0, bH[2], bH[3]);
                MMA16816(acc[0][n1], aL0, bH[2], bH[3]);
                MMA16816(acc[0][n1], aH0, bL[2], bL[3]);
                MMA16816(acc[1][n1], aH1, bH[2], bH[3]);
                MMA16816(acc[1][n1], aL1, bH[2], bH[3]);
                MMA16816(acc[1][n1], aH1, bL[2], bL[3]);
            }
        }
    }

    if (cur_t >= 0) flush_acc(acc, cur_t, warp, lane);
}

// ---------------- reduce slabs + bias (+relu) ----------------
__global__ void reduce_kernel(const float* __restrict__ bias,
                              float* __restrict__ out, int do_relu) {
    int i = blockIdx.x * blockDim.x + threadIdx.x;
    const int n4 = N_NODES * D / 4;
    if (i >= n4) return;
    const float4* p4 = (const float4*)g_partial;
    float4 s = p4[i];
    #pragma unroll
    for (int k = 1; k < NSLAB; k++) {
        float4 t = p4[i + (size_t)k * n4];
        s.x += t.x; s.y += t.y; s.z += t.z; s.w += t.w;
    }
    float4 b = ((const float4*)bias)[i & 31];
    s.x += b.x; s.y += b.y; s.z += b.z; s.w += b.w;
    if (do_relu) {
        s.x = fmaxf(s.x, 0.f); s.y = fmaxf(s.y, 0.f);
        s.z = fmaxf(s.z, 0.f); s.w = fmaxf(s.w, 0.f);
    }
    ((float4*)out)[i] = s;
}

// ---------------- scoring: warp per batch item ----------------
__global__ void score_kernel(const int* __restrict__ batch,
                             const float* __restrict__ xn,
                             const float* __restrict__ rels,
                             float* __restrict__ out) {
    int w = (blockIdx.x * blockDim.x + threadIdx.x) >> 5;
    int lane = threadIdx.x & 31;
    if (w >= N_BATCH) return;
    int bs = batch[w*3+0], bp = batch[w*3+1], bo = batch[w*3+2];
    float4 a = ((const float4*)(xn + (size_t)bs * D))[lane];
    float4 r = ((const float4*)(rels + (size_t)bp * D))[lane];
    float4 c = ((const float4*)(xn + (size_t)bo * D))[lane];
    float s = a.x*r.x*c.x + a.y*r.y*c.y + a.z*r.z*c.z + a.w*r.w*c.w;
    #pragma unroll
    for (int o = 16; o; o >>= 1) s += __shfl_xor_sync(0xffffffffu, s, o);
    if (lane == 0) out[w] = s;
}

// ---------------- launch ----------------
extern "C" void kernel_launch(void* const* d_in, const int* in_sizes, int n_in,
                              void* d_out, int out_size) {
    const int*   graph = (const int*)d_in[0];
    const int*   batch = (const int*)d_in[1];
    const float* x0    = (const float*)d_in[2];
    const float* W1    = (const float*)d_in[3];
    const float* b1    = (const float*)d_in[4];
    const float* W2    = (const float*)d_in[5];
    const float* b2    = (const float*)d_in[6];
    const float* rels  = (const float*)d_in[7];
    float* out = (float*)d_out;

    void *p_h1 = nullptr, *p_h2 = nullptr;
    cudaGetSymbolAddress(&p_h1, g_h1);
    cudaGetSymbolAddress(&p_h2, g_h2);
    float* h1 = (float*)p_h1;
    float* h2 = (float*)p_h2;

    cudaFuncSetAttribute(layer_tc_kernel,
                         cudaFuncAttributeMaxDynamicSharedMemorySize, SMEM_TOT);

    // CSR build (shared by both layers)
    zero_deg_kernel<<<(N_SEG + 255) / 256, 256>>>();
    hist_kernel<<<(E_AUG + 255) / 256, 256>>>(graph);
    scan_local_kernel<<<NB_SCAN, SCAN_B>>>();
    scan_sums_kernel<<<1, SCAN_B>>>();
    scan_add_kernel<<<NB_SCAN, SCAN_B>>>();
    scatter_kernel<<<(E_AUG + 255) / 256, 256>>>(graph);

    const int zp_grid = (NSLAB * N_NODES * D / 4 + 255) / 256;
    const int rd_grid = (N_NODES * D / 4 + 255) / 256;

    // layer 1
    convert_w_kernel<<<R_AUG, 256>>>(W1);
    zero_partial_kernel<<<zp_grid, 256>>>();
    layer_tc_kernel<<<NCTA, 256, SMEM_TOT>>>(x0);
    reduce_kernel<<<rd_grid, 256>>>(b1, h1, 1);

    // layer 2
    convert_w_kernel<<<R_AUG, 256>>>(W2);
    zero_partial_kernel<<<zp_grid, 256>>>();
    layer_tc_kernel<<<NCTA, 256, SMEM_TOT>>>(h1);
    reduce_kernel<<<rd_grid, 256>>>(b2, h2, 0);

    // scoring
    score_kernel<<<(N_BATCH * 32) / 256, 256>>>(batch, h2, rels, out);
}

// round 7
// speedup vs baseline: 2.2464x; 1.4738x over previous
#include <cuda_runtime.h>
#include <cuda_bf16.h>

// ---------------- problem constants ----------------
#define N_NODES 10000
#define N_RELS  50
#define R_AUG   101                    // 2*N_RELS + 1
#define D       128
#define N_EDGES 320000
#define E_AUG   (2*N_EDGES + N_NODES)  // 650000
#define N_SEG   (R_AUG * N_NODES)      // 1010000
#define N_BATCH 65536

// scan config
#define SCAN_B  1024
#define NB_SCAN ((N_SEG + SCAN_B - 1) / SCAN_B)   // 987

// persistent layer config
#define TM      128
#define NTILES  ((N_NODES + TM - 1) / TM)          // 79
#define NITEMS  (NTILES * R_AUG)                   // 7979
#define NCTA    148
#define WPC     ((NITEMS + NCTA - 1) / NCTA)       // 54
#define NSLAB   3

// bf16 tile row stride: 128 + 8 pad = 136 elements = 272 bytes (17 * 16B)
#define TS      272

// smem layout (bytes) — four bf16 tiles only
#define OFF_AH   0                          // bf16 A hi [128][136]  34816
#define OFF_AL   34816                      // bf16 A lo             34816
#define OFF_BH   (OFF_AL + 34816)           // bf16 B hi (Wr^T)      34816
#define OFF_BL   (OFF_BH + 34816)           // bf16 B lo             34816
#define SMEM_TOT (OFF_BL + 34816 + 64)      // ~136.1 KB

typedef unsigned long long u64;
typedef unsigned int u32;
typedef unsigned short u16;

// ---------------- static device scratch ----------------
__device__ int   g_deg[N_SEG];
__device__ int   g_rowptr[N_SEG + 1];
__device__ int   g_cursor[N_SEG];
__device__ int   g_bsums[NB_SCAN];
__device__ int   g_csr[E_AUG];                         // src only
__device__ u16   g_Bt[(size_t)R_AUG * 32768];          // per rel: hi[128][128] | lo[128][128], row=n, col=k
__device__ float g_h1[N_NODES * D];
__device__ float g_h2[N_NODES * D];
__device__ float g_partial[(size_t)NSLAB * N_NODES * D];

// ---------------- small helpers ----------------
__device__ __forceinline__ u32 smem_u32(const void* p) {
    u32 a;
    asm("{ .reg .u64 t; cvta.to.shared.u64 t, %1; cvt.u32.u64 %0, t; }" : "=r"(a) : "l"(p));
    return a;
}
__device__ __forceinline__ u16 f2bf(float v) {
    return __bfloat16_as_ushort(__float2bfloat16_rn(v));
}
__device__ __forceinline__ float bf2f(u16 u) {
    return __bfloat162float(__ushort_as_bfloat16(u));
}

#define LDSM4(r, addr)                                                          \
    asm volatile("ldmatrix.sync.aligned.m8n8.x4.shared.b16 {%0,%1,%2,%3}, [%4];"\
        : "=r"((r)[0]), "=r"((r)[1]), "=r"((r)[2]), "=r"((r)[3]) : "r"(addr))

#define MMA16816(c, a, b0_, b1_)                                                \
    asm volatile("mma.sync.aligned.m16n8k16.row.col.f32.bf16.bf16.f32 "         \
        "{%0,%1,%2,%3}, {%4,%5,%6,%7}, {%8,%9}, {%0,%1,%2,%3};"                 \
        : "+f"((c)[0]), "+f"((c)[1]), "+f"((c)[2]), "+f"((c)[3])                \
        : "r"((a)[0]), "r"((a)[1]), "r"((a)[2]), "r"((a)[3]), "r"(b0_), "r"(b1_))

// ---------------- CSR build ----------------
__global__ void zero_deg_kernel() {
    int i = blockIdx.x * blockDim.x + threadIdx.x;
    if (i < N_SEG) g_deg[i] = 0;
}

__device__ __forceinline__ void aug_edge(const int* __restrict__ g, int e,
                                         int& seg, int& src) {
    if (e < N_EDGES) {
        int s = g[e*3+0], p = g[e*3+1], o = g[e*3+2];
        seg = p * N_NODES + o;  src = s;
    } else if (e < 2*N_EDGES) {
        int e2 = e - N_EDGES;
        int s = g[e2*3+0], p = g[e2*3+1], o = g[e2*3+2];
        seg = (p + N_RELS) * N_NODES + s;  src = o;
    } else {
        int i = e - 2*N_EDGES;
        seg = 2*N_RELS*N_NODES + i;  src = i;
    }
}

__global__ void hist_kernel(const int* __restrict__ g) {
    int e = blockIdx.x * blockDim.x + threadIdx.x;
    if (e >= E_AUG) return;
    int seg, src;
    aug_edge(g, e, seg, src);
    atomicAdd(&g_deg[seg], 1);
}

__global__ __launch_bounds__(SCAN_B) void scan_local_kernel() {
    __shared__ int sm[SCAN_B];
    int tid = threadIdx.x;
    int gidx = blockIdx.x * SCAN_B + tid;
    int v = (gidx < N_SEG) ? g_deg[gidx] : 0;
    sm[tid] = v;
    __syncthreads();
    #pragma unroll
    for (int off = 1; off < SCAN_B; off <<= 1) {
        int t = (tid >= off) ? sm[tid - off] : 0;
        __syncthreads();
        sm[tid] += t;
        __syncthreads();
    }
    int incl = sm[tid];
    if (gidx < N_SEG) g_rowptr[gidx] = incl - v;
    if (tid == SCAN_B - 1) g_bsums[blockIdx.x] = incl;
}

__global__ __launch_bounds__(SCAN_B) void scan_sums_kernel() {
    __shared__ int sm[SCAN_B];
    int tid = threadIdx.x;
    int v = (tid < NB_SCAN) ? g_bsums[tid] : 0;
    sm[tid] = v;
    __syncthreads();
    #pragma unroll
    for (int off = 1; off < SCAN_B; off <<= 1) {
        int t = (tid >= off) ? sm[tid - off] : 0;
        __syncthreads();
        sm[tid] += t;
        __syncthreads();
    }
    if (tid < NB_SCAN) g_bsums[tid] = sm[tid] - v;
}

__global__ __launch_bounds__(SCAN_B) void scan_add_kernel() {
    int tid = threadIdx.x;
    int gidx = blockIdx.x * SCAN_B + tid;
    if (gidx < N_SEG) {
        int v = g_rowptr[gidx] + g_bsums[blockIdx.x];
        g_rowptr[gidx] = v;
        g_cursor[gidx] = v;
    }
    if (blockIdx.x == 0 && tid == 0) g_rowptr[N_SEG] = E_AUG;
}

__global__ void scatter_kernel(const int* __restrict__ g) {
    int e = blockIdx.x * blockDim.x + threadIdx.x;
    if (e >= E_AUG) return;
    int seg, src;
    aug_edge(g, e, seg, src);
    int pos = atomicAdd(&g_cursor[seg], 1);
    g_csr[pos] = src;
}

// ---------------- W -> bf16 hi/lo B^T planes (row=n, col=k) ----------------
__global__ void convert_w_kernel(const float* __restrict__ W) {
    int r = blockIdx.x;
    const float* Wr = W + (size_t)r * (D * D);
    u16* Bt = g_Bt + (size_t)r * 32768;
    for (int idx = threadIdx.x; idx < D * D; idx += blockDim.x) {
        int k = idx >> 7, n = idx & 127;
        float v = Wr[k * D + n];
        u16 h = f2bf(v);
        u16 l = f2bf(v - bf2f(h));
        Bt[n * D + k]         = h;
        Bt[16384 + n * D + k] = l;
    }
}

__global__ void zero_partial_kernel() {
    int i = blockIdx.x * blockDim.x + threadIdx.x;
    const int n4 = NSLAB * N_NODES * D / 4;
    if (i < n4) ((float4*)g_partial)[i] = make_float4(0.f, 0.f, 0.f, 0.f);
}

// ---------------- flush register accumulators to a partial slab ----------------
__device__ __forceinline__ void flush_acc(float acc[2][8][4], int cur_t,
                                          int warp, int lane) {
    int slab_i = blockIdx.x - (cur_t * R_AUG) / WPC;
    float* slab = g_partial + (size_t)slab_i * (N_NODES * D);
    int wm = warp & 3, wn = warp >> 2;
    int r0 = cur_t * TM + wm * 32 + (lane >> 2);
    int cb = wn * 64 + (lane & 3) * 2;
    #pragma unroll
    for (int mf = 0; mf < 2; mf++) {
        int rowA = r0 + mf * 16;
        int rowB = rowA + 8;
        #pragma unroll
        for (int nf = 0; nf < 8; nf++) {
            int col = cb + nf * 8;
            if (rowA < N_NODES)
                *(float2*)(slab + (size_t)rowA * D + col) =
                    make_float2(acc[mf][nf][0], acc[mf][nf][1]);
            if (rowB < N_NODES)
                *(float2*)(slab + (size_t)rowB * D + col) =
                    make_float2(acc[mf][nf][2], acc[mf][nf][3]);
        }
    }
}

// ---------------- persistent fused aggregate + HMMA split-bf16 GEMM ----------------
// Build: 4 threads per node-row (each owns 32 dims in 8 float4 registers);
// walk the CSR span serially (mean deg 0.64), no atomics, no fp32 staging.
// Convert+write bf16 hi/lo tiles straight from registers.
extern "C" __global__ void __launch_bounds__(256, 1)
layer_tc_kernel(const float* __restrict__ x) {
    extern __shared__ char smem[];
    u32 smb = smem_u32(smem);

    int tid  = threadIdx.x;
    int warp = tid >> 5, lane = tid & 31;
    int wm = warp & 3, wn = warp >> 2;

    // ldmatrix per-lane row offsets (bytes) within a tile
    u32 rowa = (u32)(wm * 32 + (lane & 15)) * TS + (u32)((lane >> 4) << 3) * 2;
    u32 rowb = (u32)(wn * 64 + ((lane >> 4) << 3) + (lane & 7)) * TS
             + (u32)(((lane >> 3) & 1) << 3) * 2;
    u32 aHb = smb + OFF_AH + rowa, aLb = smb + OFF_AL + rowa;
    u32 bHb = smb + OFF_BH + rowb, bLb = smb + OFF_BL + rowb;

    // build-phase role: 4 threads per row
    int bsub = tid & 3;            // 32-dim chunk
    int brow_lo = tid >> 2;        // rows 0..63 (pass 0) / +64 (pass 1)

    float acc[2][8][4];
    #pragma unroll
    for (int i = 0; i < 2; i++)
        #pragma unroll
        for (int j = 0; j < 8; j++)
            #pragma unroll
            for (int q = 0; q < 4; q++) acc[i][j][q] = 0.f;

    int i0 = blockIdx.x * WPC;
    int i1 = min(i0 + WPC, NITEMS);
    if (i0 >= i1) return;

    int cur_t = -1;

    for (int it = i0; it < i1; ++it) {
        int t = it / R_AUG, r = it - t * R_AUG;
        int tb = t * TM;
        int nrows = min(TM, N_NODES - tb);
        int segbase = r * N_NODES + tb;

        if (t != cur_t) {
            if (cur_t >= 0) {
                flush_acc(acc, cur_t, warp, lane);
                #pragma unroll
                for (int i = 0; i < 2; i++)
                    #pragma unroll
                    for (int j = 0; j < 8; j++)
                        #pragma unroll
                        for (int q = 0; q < 4; q++) acc[i][j][q] = 0.f;
            }
            cur_t = t;
        }

        __syncthreads();   // previous GEMM done reading tiles

        // ---- (A) build + convert A tiles, register-resident, no atomics ----
        #pragma unroll
        for (int p = 0; p < 2; p++) {
            int row = brow_lo + p * 64;
            float4 a[8];
            #pragma unroll
            for (int q = 0; q < 8; q++) a[q] = make_float4(0.f, 0.f, 0.f, 0.f);
            int deg = 0;
            if (row < nrows) {
                int seg = segbase + row;
                int s = g_rowptr[seg], e = g_rowptr[seg + 1];
                deg = e - s;
                for (int j = s; j < e; ++j) {
                    int src = g_csr[j];
                    const float4* v = (const float4*)(x + (size_t)src * D + (bsub << 5));
                    #pragma unroll
                    for (int q = 0; q < 8; q++) {
                        float4 w = v[q];
                        a[q].x += w.x; a[q].y += w.y; a[q].z += w.z; a[q].w += w.w;
                    }
                }
            }
            float nrm = 1.0f / fmaxf((float)deg, 1.0f);
            u32* AH = (u32*)(smem + OFF_AH + row * TS + (bsub << 6));
            u32* AL = (u32*)(smem + OFF_AL + row * TS + (bsub << 6));
            #pragma unroll
            for (int q = 0; q < 8; q++) {
                float v0 = a[q].x * nrm, v1 = a[q].y * nrm;
                float v2 = a[q].z * nrm, v3 = a[q].w * nrm;
                u16 h0 = f2bf(v0), h1 = f2bf(v1), h2 = f2bf(v2), h3 = f2bf(v3);
                u16 l0 = f2bf(v0 - bf2f(h0)), l1 = f2bf(v1 - bf2f(h1));
                u16 l2 = f2bf(v2 - bf2f(h2)), l3 = f2bf(v3 - bf2f(h3));
                AH[q*2+0] = (u32)h0 | ((u32)h1 << 16);
                AH[q*2+1] = (u32)h2 | ((u32)h3 << 16);
                AL[q*2+0] = (u32)l0 | ((u32)l1 << 16);
                AL[q*2+1] = (u32)l2 | ((u32)l3 << 16);
            }
        }

        // ---- (B) stage B hi/lo tiles (re-pad 256B rows -> 272B rows) ----
        {
            const uint4* srcH = (const uint4*)(g_Bt + (size_t)r * 32768);
            const uint4* srcL = (const uint4*)(g_Bt + (size_t)r * 32768 + 16384);
            #pragma unroll
            for (int q = 0; q < 8; q++) {
                int idx = tid + q * 256;            // 0..2047 uint4
                int row = idx >> 4, c16 = idx & 15;
                *(uint4*)(smem + OFF_BH + row * TS + c16 * 16) = srcH[idx];
                *(uint4*)(smem + OFF_BL + row * TS + c16 * 16) = srcL[idx];
            }
        }
        __syncthreads();

        // ---- (C) 128x128x128 GEMM, 3-term bf16 split on HMMA ----
        #pragma unroll
        for (int ks = 0; ks < 8; ks++) {
            u32 k2 = (u32)ks * 32;                  // k0 * 2 bytes
            u32 aH0[4], aH1[4], aL0[4], aL1[4];
            LDSM4(aH0, aHb + k2);
            LDSM4(aH1, aHb + 16 * TS + k2);
            LDSM4(aL0, aLb + k2);
            LDSM4(aL1, aLb + 16 * TS + k2);
            #pragma unroll
            for (int nf2 = 0; nf2 < 4; nf2++) {
                u32 bH[4], bL[4];
                LDSM4(bH, bHb + (u32)nf2 * 16 * TS + k2);
                LDSM4(bL, bLb + (u32)nf2 * 16 * TS + k2);
                int n0 = nf2 * 2, n1 = nf2 * 2 + 1;
                MMA16816(acc[0][n0], aH0, bH[0], bH[1]);
                MMA16816(acc[0][n0], aL0, bH[0], bH[1]);
                MMA16816(acc[0][n0], aH0, bL[0], bL[1]);
                MMA16816(acc[1][n0], aH1, bH[0], bH[1]);
                MMA16816(acc[1][n0], aL1, bH[0], bH[1]);
                MMA16816(acc[1][n0], aH1, bL[0], bL[1]);
                MMA16816(acc[0][n1], aH0, bH[2], bH[3]);
                MMA16816(acc[0][n1], aL0, bH[2], bH[3]);
                MMA16816(acc[0][n1], aH0, bL[2], bL[3]);
                MMA16816(acc[1][n1], aH1, bH[2], bH[3]);
                MMA16816(acc[1][n1], aL1, bH[2], bH[3]);
                MMA16816(acc[1][n1], aH1, bL[2], bL[3]);
            }
        }
    }

    if (cur_t >= 0) flush_acc(acc, cur_t, warp, lane);
}

// ---------------- reduce slabs + bias (+relu) ----------------
__global__ void reduce_kernel(const float* __restrict__ bias,
                              float* __restrict__ out, int do_relu) {
    int i = blockIdx.x * blockDim.x + threadIdx.x;
    const int n4 = N_NODES * D / 4;
    if (i >= n4) return;
    const float4* p4 = (const float4*)g_partial;
    float4 s = p4[i];
    #pragma unroll
    for (int k = 1; k < NSLAB; k++) {
        float4 t = p4[i + (size_t)k * n4];
        s.x += t.x; s.y += t.y; s.z += t.z; s.w += t.w;
    }
    float4 b = ((const float4*)bias)[i & 31];
    s.x += b.x; s.y += b.y; s.z += b.z; s.w += b.w;
    if (do_relu) {
        s.x = fmaxf(s.x, 0.f); s.y = fmaxf(s.y, 0.f);
        s.z = fmaxf(s.z, 0.f); s.w = fmaxf(s.w, 0.f);
    }
    ((float4*)out)[i] = s;
}

// ---------------- scoring: warp per batch item ----------------
__global__ void score_kernel(const int* __restrict__ batch,
                             const float* __restrict__ xn,
                             const float* __restrict__ rels,
                             float* __restrict__ out) {
    int w = (blockIdx.x * blockDim.x + threadIdx.x) >> 5;
    int lane = threadIdx.x & 31;
    if (w >= N_BATCH) return;
    int bs = batch[w*3+0], bp = batch[w*3+1], bo = batch[w*3+2];
    float4 a = ((const float4*)(xn + (size_t)bs * D))[lane];
    float4 r = ((const float4*)(rels + (size_t)bp * D))[lane];
    float4 c = ((const float4*)(xn + (size_t)bo * D))[lane];
    float s = a.x*r.x*c.x + a.y*r.y*c.y + a.z*r.z*c.z + a.w*r.w*c.w;
    #pragma unroll
    for (int o = 16; o; o >>= 1) s += __shfl_xor_sync(0xffffffffu, s, o);
    if (lane == 0) out[w] = s;
}

// ---------------- launch ----------------
extern "C" void kernel_launch(void* const* d_in, const int* in_sizes, int n_in,
                              void* d_out, int out_size) {
    const int*   graph = (const int*)d_in[0];
    const int*   batch = (const int*)d_in[1];
    const float* x0    = (const float*)d_in[2];
    const float* W1    = (const float*)d_in[3];
    const float* b1    = (const float*)d_in[4];
    const float* W2    = (const float*)d_in[5];
    const float* b2    = (const float*)d_in[6];
    const float* rels  = (const float*)d_in[7];
    float* out = (float*)d_out;

    void *p_h1 = nullptr, *p_h2 = nullptr;
    cudaGetSymbolAddress(&p_h1, g_h1);
    cudaGetSymbolAddress(&p_h2, g_h2);
    float* h1 = (float*)p_h1;
    float* h2 = (float*)p_h2;

    cudaFuncSetAttribute(layer_tc_kernel,
                         cudaFuncAttributeMaxDynamicSharedMemorySize, SMEM_TOT);

    // CSR build (shared by both layers)
    zero_deg_kernel<<<(N_SEG + 255) / 256, 256>>>();
    hist_kernel<<<(E_AUG + 255) / 256, 256>>>(graph);
    scan_local_kernel<<<NB_SCAN, SCAN_B>>>();
    scan_sums_kernel<<<1, SCAN_B>>>();
    scan_add_kernel<<<NB_SCAN, SCAN_B>>>();
    scatter_kernel<<<(E_AUG + 255) / 256, 256>>>(graph);

    const int zp_grid = (NSLAB * N_NODES * D / 4 + 255) / 256;
    const int rd_grid = (N_NODES * D / 4 + 255) / 256;

    // layer 1
    convert_w_kernel<<<R_AUG, 256>>>(W1);
    zero_partial_kernel<<<zp_grid, 256>>>();
    layer_tc_kernel<<<NCTA, 256, SMEM_TOT>>>(x0);
    reduce_kernel<<<rd_grid, 256>>>(b1, h1, 1);

    // layer 2
    convert_w_kernel<<<R_AUG, 256>>>(W2);
    zero_partial_kernel<<<zp_grid, 256>>>();
    layer_tc_kernel<<<NCTA, 256, SMEM_TOT>>>(h1);
    reduce_kernel<<<rd_grid, 256>>>(b2, h2, 0);

    // scoring
    score_kernel<<<(N_BATCH * 32) / 256, 256>>>(batch, h2, rels, out);
}